// round 10
// baseline (speedup 1.0000x reference)
#include <cuda_runtime.h>
#include <cuda_bf16.h>
#include <cstdint>

#define N_TOT   3072
#define NUSERS  1024
#define NITEMS  2048
#define DIM     128
#define BATCH   8192
#define GAMMA_F 0.2f
#define KSEL    64

// ---------------- device scratch (static: no allocation) ----------------
__device__ float g_A2[(size_t)N_TOT * N_TOT];
__device__ float g_A3[(size_t)N_TOT * N_TOT];
__device__ __nv_bfloat16 g_Ahi [(size_t)N_TOT * N_TOT];
__device__ __nv_bfloat16 g_Alo [(size_t)N_TOT * N_TOT];
__device__ __nv_bfloat16 g_AThi[(size_t)N_TOT * N_TOT];
__device__ __nv_bfloat16 g_ATlo[(size_t)N_TOT * N_TOT];
__device__ float g_emb [N_TOT * DIM];
__device__ float g_emb0[N_TOT * DIM];
__device__ float g_y[3 * N_TOT];
__device__ float g_coef[8];          // [0..3] attn, [4] GAMMA*(attn1+attn2+attn3)
__device__ float g_light[N_TOT * DIM];

// ===================== PTX helpers (compute_103-safe only) =====================
__device__ __forceinline__ uint32_t smem_u32(const void* p) {
    uint32_t a;
    asm("{ .reg .u64 t; cvta.to.shared.u64 t, %1; cvt.u32.u64 %0, t; }" : "=r"(a) : "l"(p));
    return a;
}
__device__ __forceinline__ void cp16(uint32_t s, const void* g) {
    uint64_t ga;
    asm("cvta.to.global.u64 %0, %1;" : "=l"(ga) : "l"(g));
    asm volatile("cp.async.cg.shared.global [%0], [%1], 16;" :: "r"(s), "l"(ga));
}
#define CP_COMMIT() asm volatile("cp.async.commit_group;" ::: "memory")

__device__ __forceinline__ void ldsm4(uint32_t* r, uint32_t addr) {
    asm volatile("ldmatrix.sync.aligned.m8n8.x4.shared.b16 {%0,%1,%2,%3}, [%4];"
                 : "=r"(r[0]), "=r"(r[1]), "=r"(r[2]), "=r"(r[3]) : "r"(addr));
}
__device__ __forceinline__ void mma16816(float* d, const uint32_t* a, const uint32_t* b) {
    asm volatile(
        "mma.sync.aligned.m16n8k16.row.col.f32.bf16.bf16.f32 "
        "{%0,%1,%2,%3}, {%4,%5,%6,%7}, {%8,%9}, {%0,%1,%2,%3};"
        : "+f"(d[0]), "+f"(d[1]), "+f"(d[2]), "+f"(d[3])
        : "r"(a[0]), "r"(a[1]), "r"(a[2]), "r"(a[3]), "r"(b[0]), "r"(b[1]));
}

// ===================== small kernels =====================
__global__ void concat_kernel(const float* __restrict__ ue, const float* __restrict__ ie,
                              const float* __restrict__ ue0, const float* __restrict__ ie0) {
    int idx = blockIdx.x * blockDim.x + threadIdx.x;
    if (idx >= N_TOT * DIM) return;
    const int split = NUSERS * DIM;
    g_emb [idx] = (idx < split) ? ue [idx] : ie [idx - split];
    g_emb0[idx] = (idx < split) ? ue0[idx] : ie0[idx - split];
}

__global__ void matvec_kernel(const float* __restrict__ A, const float* xext,
                              int xslot, int yslot) {
    int gw   = (blockIdx.x * blockDim.x + threadIdx.x) >> 5;
    int lane = threadIdx.x & 31;
    if (gw >= N_TOT) return;
    const float* x = xext ? xext : (g_y + xslot * N_TOT);
    const float4* row = reinterpret_cast<const float4*>(A + (size_t)gw * N_TOT);
    const float4* xv  = reinterpret_cast<const float4*>(x);
    float s = 0.f;
#pragma unroll 4
    for (int j = lane; j < N_TOT / 4; j += 32) {
        float4 a = row[j], b = xv[j];
        s += a.x * b.x + a.y * b.y + a.z * b.z + a.w * b.w;
    }
#pragma unroll
    for (int o = 16; o; o >>= 1) s += __shfl_xor_sync(0xffffffffu, s, o);
    if (lane == 0) g_y[yslot * N_TOT + gw] = s;
}

__global__ void weights_kernel(const float* __restrict__ u, const float* __restrict__ v) {
    __shared__ float red[8][4];
    int tid = threadIdx.x;
    float s0 = 0.f, s1 = 0.f, s2 = 0.f, s3 = 0.f;
    for (int j = tid; j < N_TOT; j += 256) {
        float uj = u[j];
        s0 += uj * v[j];
        s1 += uj * g_y[j];
        s2 += uj * g_y[N_TOT + j];
        s3 += uj * g_y[2 * N_TOT + j];
    }
#pragma unroll
    for (int o = 16; o; o >>= 1) {
        s0 += __shfl_xor_sync(0xffffffffu, s0, o);
        s1 += __shfl_xor_sync(0xffffffffu, s1, o);
        s2 += __shfl_xor_sync(0xffffffffu, s2, o);
        s3 += __shfl_xor_sync(0xffffffffu, s3, o);
    }
    if ((tid & 31) == 0) {
        int w = tid >> 5;
        red[w][0] = s0; red[w][1] = s1; red[w][2] = s2; red[w][3] = s3;
    }
    __syncthreads();
    if (tid == 0) {
        float w[4] = {0.f, 0.f, 0.f, 0.f};
        for (int p = 0; p < 8; ++p)
            for (int c = 0; c < 4; ++c) w[c] += red[p][c];
        float sum = w[0] + w[1] + w[2] + w[3];
        float wn[4], m = -1e30f;
        for (int c = 0; c < 4; ++c) { wn[c] = w[c] / sum; m = fmaxf(m, wn[c]); }
        float e[4], es = 0.f;
        for (int c = 0; c < 4; ++c) { e[c] = expf(wn[c] - m); es += e[c]; }
        float asum = 0.f;
        for (int c = 0; c < 4; ++c) { g_coef[c] = e[c] / es; if (c) asum += e[c] / es; }
        g_coef[4] = GAMMA_F * asum;
    }
}

// ---------------- split fp32 -> (hi,lo) bf16, row-major + transposed ----------------
// src_sel: 0 -> Aext (also write row-major g_Ahi/g_Alo), 1 -> g_A2 (transposed only)
__global__ void split_transpose_kernel(const float* __restrict__ Aext, int src_sel) {
    __shared__ __nv_bfloat16 th[32][33];
    __shared__ __nv_bfloat16 tl[32][33];
    const float* S = src_sel ? g_A2 : Aext;
    int tx = threadIdx.x, ty = threadIdx.y;
    int bx = blockIdx.x * 32, by = blockIdx.y * 32;
#pragma unroll
    for (int r = 0; r < 4; ++r) {
        int row = by + ty + r * 8, col = bx + tx;
        float x = S[(size_t)row * N_TOT + col];
        __nv_bfloat16 h = __float2bfloat16(x);
        __nv_bfloat16 l = __float2bfloat16(x - __bfloat162float(h));
        if (!src_sel) {
            g_Ahi[(size_t)row * N_TOT + col] = h;
            g_Alo[(size_t)row * N_TOT + col] = l;
        }
        th[ty + r * 8][tx] = h;
        tl[ty + r * 8][tx] = l;
    }
    __syncthreads();
#pragma unroll
    for (int r = 0; r < 4; ++r) {
        int row = bx + ty + r * 8, col = by + tx;
        g_AThi[(size_t)row * N_TOT + col] = th[tx][ty + r * 8];
        g_ATlo[(size_t)row * N_TOT + col] = tl[tx][ty + r * 8];
    }
}

// ===================== split-bf16 mma.sync GEMM =====================
// C = X @ Y, X(hi/lo) = g_Ahi/g_Alo [M,K] row-major (mma A, .row),
// Y^T(hi/lo) = g_AThi/g_ATlo [N,K] row-major (mma B, .col).
// CTA tile 128x128xBK32, warp tile 64x32 (2x4 warps), 3-stage cp.async pipeline.
// Smem stage (32KB): Ahi[0,8K) Alo[8K,16K) Bhi[16K,24K) Blo[24K,32K).
// Rows = 64B (32 bf16); 16B-chunk XOR swizzle: c' = c ^ ((row>>1)&3).
#define NKT   (N_TOT / 32)     // 96
#define STG_SZ 32768
#define GSMEM (3 * STG_SZ)

__global__ __launch_bounds__(256, 1)
void gemm_mma_kernel(int csel) {
    extern __shared__ char smem[];
    uint32_t sb = smem_u32(smem);
    const int tid = threadIdx.x;
    const int lane = tid & 31, wid = tid >> 5;
    const int warp_m = wid & 1, warp_n = wid >> 1;
    const int bx = blockIdx.x, by = blockIdx.y;
    float* C = csel ? g_A3 : g_A2;

    float acc[4][4][4];
#pragma unroll
    for (int mt = 0; mt < 4; ++mt)
#pragma unroll
        for (int nt = 0; nt < 4; ++nt)
#pragma unroll
            for (int e = 0; e < 4; ++e) acc[mt][nt][e] = 0.f;

    // ---- async tile loader: 8 x 16B chunks per thread ----
    auto issue_load = [&](int kt, int stage) {
        uint32_t stg = sb + stage * STG_SZ;
#pragma unroll
        for (int qq = 0; qq < 8; ++qq) {
            int id  = tid + (qq & 1) * 256;         // 0..511 within region
            int row = id >> 2, c = id & 3;
            int arr = qq >> 1;                      // 0 Ahi, 1 Alo, 2 Bhi(=AThi), 3 Blo
            int grow = ((arr < 2) ? by : bx) * 128 + row;
            const __nv_bfloat16* base =
                (arr == 0) ? g_Ahi : (arr == 1) ? g_Alo : (arr == 2) ? g_AThi : g_ATlo;
            const __nv_bfloat16* src = base + (size_t)grow * N_TOT + kt * 32 + c * 8;
            uint32_t dst = stg + arr * 8192 + row * 64 + ((c ^ ((row >> 1) & 3)) << 4);
            cp16(dst, src);
        }
        CP_COMMIT();
    };

    issue_load(0, 0);
    issue_load(1, 1);

    const int q = lane >> 3, r = lane & 7;

    for (int kt = 0; kt < NKT; ++kt) {
        int stage = kt % 3;
        if (kt >= NKT - 2) asm volatile("cp.async.wait_group 0;" ::: "memory");
        else               asm volatile("cp.async.wait_group 1;" ::: "memory");
        __syncthreads();
        uint32_t stg = sb + stage * STG_SZ;

#pragma unroll
        for (int s = 0; s < 2; ++s) {          // two k16 sub-steps of BK=32
            uint32_t ah[4][4], al[4][4], bh[2][4], bl[2][4];
            // A frags: 4 m16 tiles, hi+lo (ldmatrix.x4 each)
#pragma unroll
            for (int mt = 0; mt < 4; ++mt) {
                int arow = warp_m * 64 + mt * 16 + (q & 1) * 8 + r;
                int ac   = s * 2 + (q >> 1);
                uint32_t off = arow * 64 + ((ac ^ ((arow >> 1) & 3)) << 4);
                ldsm4(ah[mt], stg + off);
                ldsm4(al[mt], stg + 8192 + off);
            }
            // B frags: 2 ldmatrix.x4 cover 4 n8 tiles, hi+lo
#pragma unroll
            for (int p = 0; p < 2; ++p) {
                int brow = warp_n * 32 + p * 16 + (q >> 1) * 8 + r;
                int bc   = s * 2 + (q & 1);
                uint32_t off = brow * 64 + ((bc ^ ((brow >> 1) & 3)) << 4);
                ldsm4(bh[p], stg + 16384 + off);
                ldsm4(bl[p], stg + 24576 + off);
            }
            // 3-term split products into fp32 accumulators
#pragma unroll
            for (int mt = 0; mt < 4; ++mt)
#pragma unroll
                for (int nt = 0; nt < 4; ++nt) {
                    const uint32_t* Bh = &bh[nt >> 1][(nt & 1) * 2];
                    const uint32_t* Bl = &bl[nt >> 1][(nt & 1) * 2];
                    mma16816(acc[mt][nt], ah[mt], Bh);
                    mma16816(acc[mt][nt], ah[mt], Bl);
                    mma16816(acc[mt][nt], al[mt], Bh);
                }
        }
        if (kt + 2 < NKT) issue_load(kt + 2, (kt + 2) % 3);
    }

    // ---- epilogue: fp32 C fragments -> gmem ----
    int row0 = by * 128 + warp_m * 64;
    int col0 = bx * 128 + warp_n * 32;
#pragma unroll
    for (int mt = 0; mt < 4; ++mt)
#pragma unroll
        for (int nt = 0; nt < 4; ++nt) {
            int rrow = row0 + mt * 16 + (lane >> 2);
            int ccol = col0 + nt * 8 + (lane & 3) * 2;
            float2 v0 = make_float2(acc[mt][nt][0], acc[mt][nt][1]);
            float2 v1 = make_float2(acc[mt][nt][2], acc[mt][nt][3]);
            *reinterpret_cast<float2*>(C + (size_t)rrow * N_TOT + ccol)       = v0;
            *reinterpret_cast<float2*>(C + (size_t)(rrow + 8) * N_TOT + ccol) = v1;
        }
}

// ---------------- top-64 per row (3 matrices) + fused SpMM ----------------
__global__ __launch_bounds__(256)
void topk_spmm_kernel(const float* __restrict__ A) {
    __shared__ unsigned long long sred[8];
    __shared__ unsigned long long stot;
    __shared__ int   nlist;
    __shared__ int   s_col[320];
    __shared__ float s_val[320];

    int i = blockIdx.x, tid = threadIdx.x;
    const float* r0p = A    + (size_t)i * N_TOT;
    const float* r1p = g_A2 + (size_t)i * N_TOT;
    const float* r2p = g_A3 + (size_t)i * N_TOT;

    float r0[12], r1[12], r2[12];
#pragma unroll
    for (int qq = 0; qq < 12; ++qq) {
        int j = tid + qq * 256;
        r0[qq] = r0p[j]; r1[qq] = r1p[j]; r2[qq] = r2p[j];
    }
    if (tid == 0) nlist = 0;
    __syncthreads();

    unsigned lo0 = 0, lo1 = 0, lo2 = 0;
    unsigned hi0 = 0x7f800000u, hi1 = 0x7f800000u, hi2 = 0x7f800000u;
    for (int it = 0; it < 31; ++it) {
        unsigned m0 = (lo0 + hi0) >> 1, m1 = (lo1 + hi1) >> 1, m2 = (lo2 + hi2) >> 1;
        float t0 = __uint_as_float(m0), t1 = __uint_as_float(m1), t2 = __uint_as_float(m2);
        int c0 = 0, c1 = 0, c2 = 0;
#pragma unroll
        for (int qq = 0; qq < 12; ++qq) {
            c0 += (r0[qq] >= t0);
            c1 += (r1[qq] >= t1);
            c2 += (r2[qq] >= t2);
        }
        unsigned long long pc = (unsigned long long)c0
                              | ((unsigned long long)c1 << 21)
                              | ((unsigned long long)c2 << 42);
#pragma unroll
        for (int o = 16; o; o >>= 1) pc += __shfl_xor_sync(0xffffffffu, pc, o);
        if ((tid & 31) == 0) sred[tid >> 5] = pc;
        __syncthreads();
        if (tid == 0) {
            unsigned long long t = 0;
            for (int p = 0; p < 8; ++p) t += sred[p];
            stot = t;
        }
        __syncthreads();
        unsigned long long tot = stot;
        int tc0 = (int)( tot        & 0x1fffff);
        int tc1 = (int)((tot >> 21) & 0x1fffff);
        int tc2 = (int)((tot >> 42) & 0x1fffff);
        if (tc0 >= KSEL) lo0 = m0; else hi0 = m0;
        if (tc1 >= KSEL) lo1 = m1; else hi1 = m1;
        if (tc2 >= KSEL) lo2 = m2; else hi2 = m2;
    }
    float thr0 = __uint_as_float(lo0);
    float thr1 = __uint_as_float(lo1);
    float thr2 = __uint_as_float(lo2);

    float a1 = g_coef[1], a2 = g_coef[2], a3 = g_coef[3];
#pragma unroll
    for (int qq = 0; qq < 12; ++qq) {
        int j = tid + qq * 256;
        if (r0[qq] >= thr0) { int p = atomicAdd(&nlist, 1); if (p < 320) { s_col[p] = j; s_val[p] = a1 * r0[qq]; } }
        if (r1[qq] >= thr1) { int p = atomicAdd(&nlist, 1); if (p < 320) { s_col[p] = j; s_val[p] = a2 * r1[qq]; } }
        if (r2[qq] >= thr2) { int p = atomicAdd(&nlist, 1); if (p < 320) { s_col[p] = j; s_val[p] = a3 * r2[qq]; } }
    }
    __syncthreads();

    if (tid < DIM) {
        float attn0 = g_coef[0], gb = g_coef[4];
        float accv = attn0 * g_emb[i * DIM + tid] + gb * g_emb0[i * DIM + tid];
        int M = min(nlist, 320);
        for (int p = 0; p < M; ++p)
            accv += s_val[p] * g_emb[s_col[p] * DIM + tid];
        g_light[i * DIM + tid] = accv;
    }
}

// ---------------- final gather + dot (one warp per pair) ----------------
__global__ void final_kernel(const int* __restrict__ users, const int* __restrict__ items,
                             float* __restrict__ out) {
    int gw   = (blockIdx.x * blockDim.x + threadIdx.x) >> 5;
    int lane = threadIdx.x & 31;
    if (gw >= BATCH) return;
    const float4* lu = reinterpret_cast<const float4*>(g_light + (size_t)users[gw] * DIM);
    const float4* li = reinterpret_cast<const float4*>(g_light + (size_t)(NUSERS + items[gw]) * DIM);
    float4 a = lu[lane], b = li[lane];
    float s = a.x * b.x + a.y * b.y + a.z * b.z + a.w * b.w;
#pragma unroll
    for (int o = 16; o; o >>= 1) s += __shfl_xor_sync(0xffffffffu, s, o);
    if (lane == 0) out[gw] = s;
}

// ---------------- launch ----------------
extern "C" void kernel_launch(void* const* d_in, const int* in_sizes, int n_in,
                              void* d_out, int out_size) {
    const int *users = nullptr, *items = nullptr;
    const float *A = nullptr, *ue = nullptr, *ie = nullptr, *ue0 = nullptr, *ie0 = nullptr,
                *u = nullptr, *v = nullptr;
    for (int i = 0; i < n_in; ++i) {
        int sz = in_sizes[i];
        if      (sz == BATCH)          { if (!users) users = (const int*)d_in[i]; else items = (const int*)d_in[i]; }
        else if (sz == N_TOT * N_TOT)  { A = (const float*)d_in[i]; }
        else if (sz == NUSERS * DIM)   { if (!ue) ue = (const float*)d_in[i]; else ue0 = (const float*)d_in[i]; }
        else if (sz == NITEMS * DIM)   { if (!ie) ie = (const float*)d_in[i]; else ie0 = (const float*)d_in[i]; }
        else if (sz == N_TOT)          { if (!u)  u  = (const float*)d_in[i]; else v   = (const float*)d_in[i]; }
    }
    float* out = (float*)d_out;

    cudaFuncSetAttribute(gemm_mma_kernel, cudaFuncAttributeMaxDynamicSharedMemorySize, GSMEM);

    concat_kernel<<<(N_TOT * DIM + 255) / 256, 256>>>(ue, ie, ue0, ie0);

    matvec_kernel<<<N_TOT / 8, 256>>>(A, v, 0, 0);
    matvec_kernel<<<N_TOT / 8, 256>>>(A, nullptr, 0, 1);
    matvec_kernel<<<N_TOT / 8, 256>>>(A, nullptr, 1, 2);
    weights_kernel<<<1, 256>>>(u, v);

    // split A -> hi/lo (row-major for mma-A, transposed for mma-B)
    split_transpose_kernel<<<dim3(96, 96), dim3(32, 8)>>>(A, 0);
    // A2 = A @ A  (tensor cores via mma.sync, split bf16)
    gemm_mma_kernel<<<dim3(N_TOT / 128, N_TOT / 128), 256, GSMEM>>>(0);
    // B operand for GEMM2: split+transpose A2
    split_transpose_kernel<<<dim3(96, 96), dim3(32, 8)>>>(A, 1);
    // A3 = A @ A2
    gemm_mma_kernel<<<dim3(N_TOT / 128, N_TOT / 128), 256, GSMEM>>>(1);

    topk_spmm_kernel<<<N_TOT, 256>>>(A);

    final_kernel<<<BATCH * 32 / 256, 256>>>(users, items, out);
}

// round 11
// speedup vs baseline: 1.0028x; 1.0028x over previous
#include <cuda_runtime.h>
#include <cuda_bf16.h>
#include <cstdint>

#define N_TOT   3072
#define NUSERS  1024
#define NITEMS  2048
#define DIM     128
#define BATCH   8192
#define GAMMA_F 0.2f
#define KSEL    64

// ---------------- device scratch (static: no allocation) ----------------
__device__ float g_A2[(size_t)N_TOT * N_TOT];
__device__ float g_A3[(size_t)N_TOT * N_TOT];
__device__ __nv_bfloat16 g_Ahi [(size_t)N_TOT * N_TOT];
__device__ __nv_bfloat16 g_Alo [(size_t)N_TOT * N_TOT];
__device__ __nv_bfloat16 g_AThi[(size_t)N_TOT * N_TOT];
__device__ __nv_bfloat16 g_ATlo[(size_t)N_TOT * N_TOT];
__device__ float g_emb [N_TOT * DIM];
__device__ float g_emb0[N_TOT * DIM];
__device__ float g_y[3 * N_TOT];
__device__ float g_coef[8];          // [0..3] attn, [4] GAMMA*(attn1+attn2+attn3)
__device__ float g_light[N_TOT * DIM];

// ===================== PTX helpers (compute_103-safe only) =====================
__device__ __forceinline__ uint32_t smem_u32(const void* p) {
    uint32_t a;
    asm("{ .reg .u64 t; cvta.to.shared.u64 t, %1; cvt.u32.u64 %0, t; }" : "=r"(a) : "l"(p));
    return a;
}
__device__ __forceinline__ void cp16(uint32_t s, const void* g) {
    uint64_t ga;
    asm("cvta.to.global.u64 %0, %1;" : "=l"(ga) : "l"(g));
    asm volatile("cp.async.cg.shared.global [%0], [%1], 16;" :: "r"(s), "l"(ga));
}
#define CP_COMMIT() asm volatile("cp.async.commit_group;" ::: "memory")

__device__ __forceinline__ void ldsm4(uint32_t* r, uint32_t addr) {
    asm volatile("ldmatrix.sync.aligned.m8n8.x4.shared.b16 {%0,%1,%2,%3}, [%4];"
                 : "=r"(r[0]), "=r"(r[1]), "=r"(r[2]), "=r"(r[3]) : "r"(addr));
}
__device__ __forceinline__ void mma16816(float* d, const uint32_t* a, const uint32_t* b) {
    asm volatile(
        "mma.sync.aligned.m16n8k16.row.col.f32.bf16.bf16.f32 "
        "{%0,%1,%2,%3}, {%4,%5,%6,%7}, {%8,%9}, {%0,%1,%2,%3};"
        : "+f"(d[0]), "+f"(d[1]), "+f"(d[2]), "+f"(d[3])
        : "r"(a[0]), "r"(a[1]), "r"(a[2]), "r"(a[3]), "r"(b[0]), "r"(b[1]));
}

// ===================== small kernels =====================
__global__ void concat_kernel(const float* __restrict__ ue, const float* __restrict__ ie,
                              const float* __restrict__ ue0, const float* __restrict__ ie0) {
    int idx = blockIdx.x * blockDim.x + threadIdx.x;
    if (idx >= N_TOT * DIM) return;
    const int split = NUSERS * DIM;
    g_emb [idx] = (idx < split) ? ue [idx] : ie [idx - split];
    g_emb0[idx] = (idx < split) ? ue0[idx] : ie0[idx - split];
}

__global__ void matvec_kernel(const float* __restrict__ A, const float* xext,
                              int xslot, int yslot) {
    int gw   = (blockIdx.x * blockDim.x + threadIdx.x) >> 5;
    int lane = threadIdx.x & 31;
    if (gw >= N_TOT) return;
    const float* x = xext ? xext : (g_y + xslot * N_TOT);
    const float4* row = reinterpret_cast<const float4*>(A + (size_t)gw * N_TOT);
    const float4* xv  = reinterpret_cast<const float4*>(x);
    float s = 0.f;
#pragma unroll 4
    for (int j = lane; j < N_TOT / 4; j += 32) {
        float4 a = row[j], b = xv[j];
        s += a.x * b.x + a.y * b.y + a.z * b.z + a.w * b.w;
    }
#pragma unroll
    for (int o = 16; o; o >>= 1) s += __shfl_xor_sync(0xffffffffu, s, o);
    if (lane == 0) g_y[yslot * N_TOT + gw] = s;
}

__global__ void weights_kernel(const float* __restrict__ u, const float* __restrict__ v) {
    __shared__ float red[8][4];
    int tid = threadIdx.x;
    float s0 = 0.f, s1 = 0.f, s2 = 0.f, s3 = 0.f;
    for (int j = tid; j < N_TOT; j += 256) {
        float uj = u[j];
        s0 += uj * v[j];
        s1 += uj * g_y[j];
        s2 += uj * g_y[N_TOT + j];
        s3 += uj * g_y[2 * N_TOT + j];
    }
#pragma unroll
    for (int o = 16; o; o >>= 1) {
        s0 += __shfl_xor_sync(0xffffffffu, s0, o);
        s1 += __shfl_xor_sync(0xffffffffu, s1, o);
        s2 += __shfl_xor_sync(0xffffffffu, s2, o);
        s3 += __shfl_xor_sync(0xffffffffu, s3, o);
    }
    if ((tid & 31) == 0) {
        int w = tid >> 5;
        red[w][0] = s0; red[w][1] = s1; red[w][2] = s2; red[w][3] = s3;
    }
    __syncthreads();
    if (tid == 0) {
        float w[4] = {0.f, 0.f, 0.f, 0.f};
        for (int p = 0; p < 8; ++p)
            for (int c = 0; c < 4; ++c) w[c] += red[p][c];
        float sum = w[0] + w[1] + w[2] + w[3];
        float wn[4], m = -1e30f;
        for (int c = 0; c < 4; ++c) { wn[c] = w[c] / sum; m = fmaxf(m, wn[c]); }
        float e[4], es = 0.f;
        for (int c = 0; c < 4; ++c) { e[c] = expf(wn[c] - m); es += e[c]; }
        float asum = 0.f;
        for (int c = 0; c < 4; ++c) { g_coef[c] = e[c] / es; if (c) asum += e[c] / es; }
        g_coef[4] = GAMMA_F * asum;
    }
}

// ---------------- split fp32 -> (hi,lo) bf16, row-major + transposed ----------------
// src_sel: 0 -> Aext (also write row-major g_Ahi/g_Alo), 1 -> g_A2 (transposed only)
__global__ void split_transpose_kernel(const float* __restrict__ Aext, int src_sel) {
    __shared__ __nv_bfloat16 th[32][33];
    __shared__ __nv_bfloat16 tl[32][33];
    const float* S = src_sel ? g_A2 : Aext;
    int tx = threadIdx.x, ty = threadIdx.y;
    int bx = blockIdx.x * 32, by = blockIdx.y * 32;
#pragma unroll
    for (int r = 0; r < 4; ++r) {
        int row = by + ty + r * 8, col = bx + tx;
        float x = S[(size_t)row * N_TOT + col];
        __nv_bfloat16 h = __float2bfloat16(x);
        __nv_bfloat16 l = __float2bfloat16(x - __bfloat162float(h));
        if (!src_sel) {
            g_Ahi[(size_t)row * N_TOT + col] = h;
            g_Alo[(size_t)row * N_TOT + col] = l;
        }
        th[ty + r * 8][tx] = h;
        tl[ty + r * 8][tx] = l;
    }
    __syncthreads();
#pragma unroll
    for (int r = 0; r < 4; ++r) {
        int row = bx + ty + r * 8, col = by + tx;
        g_AThi[(size_t)row * N_TOT + col] = th[tx][ty + r * 8];
        g_ATlo[(size_t)row * N_TOT + col] = tl[tx][ty + r * 8];
    }
}

// ===================== split-bf16 mma.sync GEMM =====================
// C = X @ Y, X(hi/lo) = g_Ahi/g_Alo [M,K] row-major (mma A, .row),
// Y^T(hi/lo) = g_AThi/g_ATlo [N,K] row-major (mma B, .col).
// CTA tile 128x128xBK32, warp tile 64x32 (2x4 warps), 3-stage cp.async pipeline.
// Smem stage (32KB): Ahi[0,8K) Alo[8K,16K) Bhi[16K,24K) Blo[24K,32K).
// Rows = 64B (32 bf16); 16B-chunk XOR swizzle: c' = c ^ ((row>>1)&3).
#define NKT   (N_TOT / 32)     // 96
#define STG_SZ 32768
#define GSMEM (3 * STG_SZ)

__global__ __launch_bounds__(256, 1)
void gemm_mma_kernel(int csel) {
    extern __shared__ char smem[];
    uint32_t sb = smem_u32(smem);
    const int tid = threadIdx.x;
    const int lane = tid & 31, wid = tid >> 5;
    const int warp_m = wid & 1, warp_n = wid >> 1;
    const int bx = blockIdx.x, by = blockIdx.y;
    float* C = csel ? g_A3 : g_A2;

    float acc[4][4][4];
#pragma unroll
    for (int mt = 0; mt < 4; ++mt)
#pragma unroll
        for (int nt = 0; nt < 4; ++nt)
#pragma unroll
            for (int e = 0; e < 4; ++e) acc[mt][nt][e] = 0.f;

    // ---- async tile loader: 8 x 16B chunks per thread ----
    auto issue_load = [&](int kt, int stage) {
        uint32_t stg = sb + stage * STG_SZ;
#pragma unroll
        for (int qq = 0; qq < 8; ++qq) {
            int id  = tid + (qq & 1) * 256;         // 0..511 within region
            int row = id >> 2, c = id & 3;
            int arr = qq >> 1;                      // 0 Ahi, 1 Alo, 2 Bhi(=AThi), 3 Blo
            int grow = ((arr < 2) ? by : bx) * 128 + row;
            const __nv_bfloat16* base =
                (arr == 0) ? g_Ahi : (arr == 1) ? g_Alo : (arr == 2) ? g_AThi : g_ATlo;
            const __nv_bfloat16* src = base + (size_t)grow * N_TOT + kt * 32 + c * 8;
            uint32_t dst = stg + arr * 8192 + row * 64 + ((c ^ ((row >> 1) & 3)) << 4);
            cp16(dst, src);
        }
        CP_COMMIT();
    };

    issue_load(0, 0);
    issue_load(1, 1);

    const int q = lane >> 3, r = lane & 7;

    for (int kt = 0; kt < NKT; ++kt) {
        int stage = kt % 3;
        if (kt >= NKT - 2) asm volatile("cp.async.wait_group 0;" ::: "memory");
        else               asm volatile("cp.async.wait_group 1;" ::: "memory");
        __syncthreads();
        uint32_t stg = sb + stage * STG_SZ;

#pragma unroll
        for (int s = 0; s < 2; ++s) {          // two k16 sub-steps of BK=32
            uint32_t ah[4][4], al[4][4], bh[2][4], bl[2][4];
            // A frags: 4 m16 tiles, hi+lo (ldmatrix.x4 each)
#pragma unroll
            for (int mt = 0; mt < 4; ++mt) {
                int arow = warp_m * 64 + mt * 16 + (q & 1) * 8 + r;
                int ac   = s * 2 + (q >> 1);
                uint32_t off = arow * 64 + ((ac ^ ((arow >> 1) & 3)) << 4);
                ldsm4(ah[mt], stg + off);
                ldsm4(al[mt], stg + 8192 + off);
            }
            // B frags: 2 ldmatrix.x4 cover 4 n8 tiles, hi+lo
#pragma unroll
            for (int p = 0; p < 2; ++p) {
                int brow = warp_n * 32 + p * 16 + (q >> 1) * 8 + r;
                int bc   = s * 2 + (q & 1);
                uint32_t off = brow * 64 + ((bc ^ ((brow >> 1) & 3)) << 4);
                ldsm4(bh[p], stg + 16384 + off);
                ldsm4(bl[p], stg + 24576 + off);
            }
            // 3-term split products into fp32 accumulators
#pragma unroll
            for (int mt = 0; mt < 4; ++mt)
#pragma unroll
                for (int nt = 0; nt < 4; ++nt) {
                    const uint32_t* Bh = &bh[nt >> 1][(nt & 1) * 2];
                    const uint32_t* Bl = &bl[nt >> 1][(nt & 1) * 2];
                    mma16816(acc[mt][nt], ah[mt], Bh);
                    mma16816(acc[mt][nt], ah[mt], Bl);
                    mma16816(acc[mt][nt], al[mt], Bh);
                }
        }
        if (kt + 2 < NKT) issue_load(kt + 2, (kt + 2) % 3);
    }

    // ---- epilogue: fp32 C fragments -> gmem ----
    int row0 = by * 128 + warp_m * 64;
    int col0 = bx * 128 + warp_n * 32;
#pragma unroll
    for (int mt = 0; mt < 4; ++mt)
#pragma unroll
        for (int nt = 0; nt < 4; ++nt) {
            int rrow = row0 + mt * 16 + (lane >> 2);
            int ccol = col0 + nt * 8 + (lane & 3) * 2;
            float2 v0 = make_float2(acc[mt][nt][0], acc[mt][nt][1]);
            float2 v1 = make_float2(acc[mt][nt][2], acc[mt][nt][3]);
            *reinterpret_cast<float2*>(C + (size_t)rrow * N_TOT + ccol)       = v0;
            *reinterpret_cast<float2*>(C + (size_t)(rrow + 8) * N_TOT + ccol) = v1;
        }
}

// ---------------- top-64 per row (3 matrices) + fused SpMM ----------------
__global__ __launch_bounds__(256)
void topk_spmm_kernel(const float* __restrict__ A) {
    __shared__ unsigned long long sred[8];
    __shared__ unsigned long long stot;
    __shared__ int   nlist;
    __shared__ int   s_col[320];
    __shared__ float s_val[320];

    int i = blockIdx.x, tid = threadIdx.x;
    const float* r0p = A    + (size_t)i * N_TOT;
    const float* r1p = g_A2 + (size_t)i * N_TOT;
    const float* r2p = g_A3 + (size_t)i * N_TOT;

    float r0[12], r1[12], r2[12];
#pragma unroll
    for (int qq = 0; qq < 12; ++qq) {
        int j = tid + qq * 256;
        r0[qq] = r0p[j]; r1[qq] = r1p[j]; r2[qq] = r2p[j];
    }
    if (tid == 0) nlist = 0;
    __syncthreads();

    unsigned lo0 = 0, lo1 = 0, lo2 = 0;
    unsigned hi0 = 0x7f800000u, hi1 = 0x7f800000u, hi2 = 0x7f800000u;
    for (int it = 0; it < 31; ++it) {
        unsigned m0 = (lo0 + hi0) >> 1, m1 = (lo1 + hi1) >> 1, m2 = (lo2 + hi2) >> 1;
        float t0 = __uint_as_float(m0), t1 = __uint_as_float(m1), t2 = __uint_as_float(m2);
        int c0 = 0, c1 = 0, c2 = 0;
#pragma unroll
        for (int qq = 0; qq < 12; ++qq) {
            c0 += (r0[qq] >= t0);
            c1 += (r1[qq] >= t1);
            c2 += (r2[qq] >= t2);
        }
        unsigned long long pc = (unsigned long long)c0
                              | ((unsigned long long)c1 << 21)
                              | ((unsigned long long)c2 << 42);
#pragma unroll
        for (int o = 16; o; o >>= 1) pc += __shfl_xor_sync(0xffffffffu, pc, o);
        if ((tid & 31) == 0) sred[tid >> 5] = pc;
        __syncthreads();
        if (tid == 0) {
            unsigned long long t = 0;
            for (int p = 0; p < 8; ++p) t += sred[p];
            stot = t;
        }
        __syncthreads();
        unsigned long long tot = stot;
        int tc0 = (int)( tot        & 0x1fffff);
        int tc1 = (int)((tot >> 21) & 0x1fffff);
        int tc2 = (int)((tot >> 42) & 0x1fffff);
        if (tc0 >= KSEL) lo0 = m0; else hi0 = m0;
        if (tc1 >= KSEL) lo1 = m1; else hi1 = m1;
        if (tc2 >= KSEL) lo2 = m2; else hi2 = m2;
    }
    float thr0 = __uint_as_float(lo0);
    float thr1 = __uint_as_float(lo1);
    float thr2 = __uint_as_float(lo2);

    float a1 = g_coef[1], a2 = g_coef[2], a3 = g_coef[3];
#pragma unroll
    for (int qq = 0; qq < 12; ++qq) {
        int j = tid + qq * 256;
        if (r0[qq] >= thr0) { int p = atomicAdd(&nlist, 1); if (p < 320) { s_col[p] = j; s_val[p] = a1 * r0[qq]; } }
        if (r1[qq] >= thr1) { int p = atomicAdd(&nlist, 1); if (p < 320) { s_col[p] = j; s_val[p] = a2 * r1[qq]; } }
        if (r2[qq] >= thr2) { int p = atomicAdd(&nlist, 1); if (p < 320) { s_col[p] = j; s_val[p] = a3 * r2[qq]; } }
    }
    __syncthreads();

    if (tid < DIM) {
        float attn0 = g_coef[0], gb = g_coef[4];
        float accv = attn0 * g_emb[i * DIM + tid] + gb * g_emb0[i * DIM + tid];
        int M = min(nlist, 320);
        for (int p = 0; p < M; ++p)
            accv += s_val[p] * g_emb[s_col[p] * DIM + tid];
        g_light[i * DIM + tid] = accv;
    }
}

// ---------------- final gather + dot (one warp per pair) ----------------
__global__ void final_kernel(const int* __restrict__ users, const int* __restrict__ items,
                             float* __restrict__ out) {
    int gw   = (blockIdx.x * blockDim.x + threadIdx.x) >> 5;
    int lane = threadIdx.x & 31;
    if (gw >= BATCH) return;
    const float4* lu = reinterpret_cast<const float4*>(g_light + (size_t)users[gw] * DIM);
    const float4* li = reinterpret_cast<const float4*>(g_light + (size_t)(NUSERS + items[gw]) * DIM);
    float4 a = lu[lane], b = li[lane];
    float s = a.x * b.x + a.y * b.y + a.z * b.z + a.w * b.w;
#pragma unroll
    for (int o = 16; o; o >>= 1) s += __shfl_xor_sync(0xffffffffu, s, o);
    if (lane == 0) out[gw] = s;
}

// ---------------- launch ----------------
extern "C" void kernel_launch(void* const* d_in, const int* in_sizes, int n_in,
                              void* d_out, int out_size) {
    const int *users = nullptr, *items = nullptr;
    const float *A = nullptr, *ue = nullptr, *ie = nullptr, *ue0 = nullptr, *ie0 = nullptr,
                *u = nullptr, *v = nullptr;
    for (int i = 0; i < n_in; ++i) {
        int sz = in_sizes[i];
        if      (sz == BATCH)          { if (!users) users = (const int*)d_in[i]; else items = (const int*)d_in[i]; }
        else if (sz == N_TOT * N_TOT)  { A = (const float*)d_in[i]; }
        else if (sz == NUSERS * DIM)   { if (!ue) ue = (const float*)d_in[i]; else ue0 = (const float*)d_in[i]; }
        else if (sz == NITEMS * DIM)   { if (!ie) ie = (const float*)d_in[i]; else ie0 = (const float*)d_in[i]; }
        else if (sz == N_TOT)          { if (!u)  u  = (const float*)d_in[i]; else v   = (const float*)d_in[i]; }
    }
    float* out = (float*)d_out;

    cudaFuncSetAttribute(gemm_mma_kernel, cudaFuncAttributeMaxDynamicSharedMemorySize, GSMEM);

    concat_kernel<<<(N_TOT * DIM + 255) / 256, 256>>>(ue, ie, ue0, ie0);

    matvec_kernel<<<N_TOT / 8, 256>>>(A, v, 0, 0);
    matvec_kernel<<<N_TOT / 8, 256>>>(A, nullptr, 0, 1);
    matvec_kernel<<<N_TOT / 8, 256>>>(A, nullptr, 1, 2);
    weights_kernel<<<1, 256>>>(u, v);

    // split A -> hi/lo (row-major for mma-A, transposed for mma-B)
    split_transpose_kernel<<<dim3(96, 96), dim3(32, 8)>>>(A, 0);
    // A2 = A @ A  (tensor cores via mma.sync, split bf16)
    gemm_mma_kernel<<<dim3(N_TOT / 128, N_TOT / 128), 256, GSMEM>>>(0);
    // B operand for GEMM2: split+transpose A2
    split_transpose_kernel<<<dim3(96, 96), dim3(32, 8)>>>(A, 1);
    // A3 = A @ A2
    gemm_mma_kernel<<<dim3(N_TOT / 128, N_TOT / 128), 256, GSMEM>>>(1);

    topk_spmm_kernel<<<N_TOT, 256>>>(A);

    final_kernel<<<BATCH * 32 / 256, 256>>>(users, items, out);
}